// round 15
// baseline (speedup 1.0000x reference)
#include <cuda_runtime.h>
#include <cuda_bf16.h>

// HairBundleSDE: element-wise RHS of a 5-state SDE over 8,388,608 rows.
// Pure streaming kernel: 167.8 MB in + 167.8 MB out. Strategy: 4 rows
// (20 floats = 80 bytes, always 16B-aligned) per thread via 5x float4
// loads/stores, fully coalesced at the sector level.

#define OMEGA_F   6.28318530717958647692f
#define AMP_F     0.3f

__device__ __forceinline__ void row_rhs(float X, float Xa, float pm, float pgs, float pt,
                                        float force,
                                        float& dX, float& dXa, float& dpm, float& dpgs, float& dpt)
{
    // p_open = sigmoid((X - Xa - D0)/DELTA),  D0=0.5, DELTA=0.2  -> *5
    float z = (X - Xa - 0.5f) * 5.0f;
    float p = 1.0f / (1.0f + __expf(-z));
    // f_gs = K_GS*(X - Xa - D0*p_open), K_GS=0.75
    float fgs = 0.75f * (X - Xa - 0.5f * p);
    // dX = (-f_gs - K_SP*X)/LAM + force, LAM=1, K_SP=0.6
    dX = -fgs - 0.6f * X + force;
    // dXa = (f_gs - F_MAX*(1 - S_CA*pm))/LAM_A, F_MAX=1, S_CA=0.7, LAM_A=10
    dXa = (fgs - (1.0f - 0.7f * pm)) * 0.1f;
    // dpm = (C_M*p*(1-pm) - pm)/TAU_M, C_M=1.5, TAU_M=1
    dpm = 1.5f * p * (1.0f - pm) - pm;
    // dpgs = (C_GS*p*(1-pgs) - pgs)/TAU_GS, C_GS=1.2, TAU_GS=5
    dpgs = (1.2f * p * (1.0f - pgs) - pgs) * 0.2f;
    // dpt = (C_T*p*(1-pt) - pt)/TAU_T, C_T=0.8, TAU_T=10
    dpt = (0.8f * p * (1.0f - pt) - pt) * 0.1f;
}

__global__ void __launch_bounds__(256)
hb_sde_quad_kernel(const float4* __restrict__ x4,
                   const float* __restrict__ t,
                   float4* __restrict__ o4,
                   int n_quads)
{
    int i = blockIdx.x * blockDim.x + threadIdx.x;
    if (i >= n_quads) return;

    float force = AMP_F * sinf(OMEGA_F * t[0]);

    // 4 rows = 20 floats = 5 aligned float4s (base byte offset 80*i, 16B aligned)
    long base = (long)i * 5;
    float4 a = x4[base + 0];
    float4 b = x4[base + 1];
    float4 c = x4[base + 2];
    float4 d = x4[base + 3];
    float4 e = x4[base + 4];

    float v[20] = { a.x, a.y, a.z, a.w,
                    b.x, b.y, b.z, b.w,
                    c.x, c.y, c.z, c.w,
                    d.x, d.y, d.z, d.w,
                    e.x, e.y, e.z, e.w };
    float o[20];

#pragma unroll
    for (int r = 0; r < 4; ++r) {
        row_rhs(v[5*r + 0], v[5*r + 1], v[5*r + 2], v[5*r + 3], v[5*r + 4],
                force,
                o[5*r + 0], o[5*r + 1], o[5*r + 2], o[5*r + 3], o[5*r + 4]);
    }

    o4[base + 0] = make_float4(o[0],  o[1],  o[2],  o[3]);
    o4[base + 1] = make_float4(o[4],  o[5],  o[6],  o[7]);
    o4[base + 2] = make_float4(o[8],  o[9],  o[10], o[11]);
    o4[base + 3] = make_float4(o[12], o[13], o[14], o[15]);
    o4[base + 4] = make_float4(o[16], o[17], o[18], o[19]);
}

// Scalar tail for n % 4 != 0 (not hit at N=8388608, kept for robustness).
__global__ void __launch_bounds__(128)
hb_sde_tail_kernel(const float* __restrict__ x,
                   const float* __restrict__ t,
                   float* __restrict__ out,
                   int start, int n)
{
    int i = start + blockIdx.x * blockDim.x + threadIdx.x;
    if (i >= n) return;

    float force = AMP_F * sinf(OMEGA_F * t[0]);
    long b = (long)i * 5;
    float dX, dXa, dpm, dpgs, dpt;
    row_rhs(x[b+0], x[b+1], x[b+2], x[b+3], x[b+4], force,
            dX, dXa, dpm, dpgs, dpt);
    out[b+0] = dX;  out[b+1] = dXa; out[b+2] = dpm;
    out[b+3] = dpgs; out[b+4] = dpt;
}

extern "C" void kernel_launch(void* const* d_in, const int* in_sizes, int n_in,
                              void* d_out, int out_size)
{
    // Identify inputs by size: t has 1 element, x has N*5.
    const float* t_ptr = nullptr;
    const float* x_ptr = nullptr;
    int x_elems = 0;
    for (int k = 0; k < n_in; ++k) {
        if (in_sizes[k] == 1) { t_ptr = (const float*)d_in[k]; }
        else                  { x_ptr = (const float*)d_in[k]; x_elems = in_sizes[k]; }
    }

    int n = x_elems / 5;           // number of rows
    int n_quads = n / 4;           // 4 rows per thread
    int tail_start = n_quads * 4;

    if (n_quads > 0) {
        int threads = 256;
        int blocks = (n_quads + threads - 1) / threads;
        hb_sde_quad_kernel<<<blocks, threads>>>(
            (const float4*)x_ptr, t_ptr, (float4*)d_out, n_quads);
    }
    if (tail_start < n) {
        int tail = n - tail_start;
        hb_sde_tail_kernel<<<(tail + 127) / 128, 128>>>(
            x_ptr, t_ptr, (float*)d_out, tail_start, n);
    }
}

// round 16
// speedup vs baseline: 1.0224x; 1.0224x over previous
#include <cuda_runtime.h>
#include <cuda_bf16.h>

// HairBundleSDE: element-wise RHS of a 5-state SDE over 8,388,608 rows.
// Pure streaming kernel: 167.8 MB in + 167.8 MB out. Strategy: 4 rows
// (20 floats = 80 bytes, always 16B-aligned) per thread via 5x float4
// loads/stores, fully coalesced at the sector level.

#define OMEGA_F   6.28318530717958647692f
#define AMP_F     0.3f

__device__ __forceinline__ void row_rhs(float X, float Xa, float pm, float pgs, float pt,
                                        float force,
                                        float& dX, float& dXa, float& dpm, float& dpgs, float& dpt)
{
    // p_open = sigmoid((X - Xa - D0)/DELTA),  D0=0.5, DELTA=0.2  -> *5
    float z = (X - Xa - 0.5f) * 5.0f;
    float p = 1.0f / (1.0f + __expf(-z));
    // f_gs = K_GS*(X - Xa - D0*p_open), K_GS=0.75
    float fgs = 0.75f * (X - Xa - 0.5f * p);
    // dX = (-f_gs - K_SP*X)/LAM + force, LAM=1, K_SP=0.6
    dX = -fgs - 0.6f * X + force;
    // dXa = (f_gs - F_MAX*(1 - S_CA*pm))/LAM_A, F_MAX=1, S_CA=0.7, LAM_A=10
    dXa = (fgs - (1.0f - 0.7f * pm)) * 0.1f;
    // dpm = (C_M*p*(1-pm) - pm)/TAU_M, C_M=1.5, TAU_M=1
    dpm = 1.5f * p * (1.0f - pm) - pm;
    // dpgs = (C_GS*p*(1-pgs) - pgs)/TAU_GS, C_GS=1.2, TAU_GS=5
    dpgs = (1.2f * p * (1.0f - pgs) - pgs) * 0.2f;
    // dpt = (C_T*p*(1-pt) - pt)/TAU_T, C_T=0.8, TAU_T=10
    dpt = (0.8f * p * (1.0f - pt) - pt) * 0.1f;
}

__global__ void __launch_bounds__(256)
hb_sde_quad_kernel(const float4* __restrict__ x4,
                   const float* __restrict__ t,
                   float4* __restrict__ o4,
                   int n_quads)
{
    int i = blockIdx.x * blockDim.x + threadIdx.x;
    if (i >= n_quads) return;

    float force = AMP_F * sinf(OMEGA_F * t[0]);

    // 4 rows = 20 floats = 5 aligned float4s (base byte offset 80*i, 16B aligned)
    long base = (long)i * 5;
    float4 a = x4[base + 0];
    float4 b = x4[base + 1];
    float4 c = x4[base + 2];
    float4 d = x4[base + 3];
    float4 e = x4[base + 4];

    float v[20] = { a.x, a.y, a.z, a.w,
                    b.x, b.y, b.z, b.w,
                    c.x, c.y, c.z, c.w,
                    d.x, d.y, d.z, d.w,
                    e.x, e.y, e.z, e.w };
    float o[20];

#pragma unroll
    for (int r = 0; r < 4; ++r) {
        row_rhs(v[5*r + 0], v[5*r + 1], v[5*r + 2], v[5*r + 3], v[5*r + 4],
                force,
                o[5*r + 0], o[5*r + 1], o[5*r + 2], o[5*r + 3], o[5*r + 4]);
    }

    o4[base + 0] = make_float4(o[0],  o[1],  o[2],  o[3]);
    o4[base + 1] = make_float4(o[4],  o[5],  o[6],  o[7]);
    o4[base + 2] = make_float4(o[8],  o[9],  o[10], o[11]);
    o4[base + 3] = make_float4(o[12], o[13], o[14], o[15]);
    o4[base + 4] = make_float4(o[16], o[17], o[18], o[19]);
}

// Scalar tail for n % 4 != 0 (not hit at N=8388608, kept for robustness).
__global__ void __launch_bounds__(128)
hb_sde_tail_kernel(const float* __restrict__ x,
                   const float* __restrict__ t,
                   float* __restrict__ out,
                   int start, int n)
{
    int i = start + blockIdx.x * blockDim.x + threadIdx.x;
    if (i >= n) return;

    float force = AMP_F * sinf(OMEGA_F * t[0]);
    long b = (long)i * 5;
    float dX, dXa, dpm, dpgs, dpt;
    row_rhs(x[b+0], x[b+1], x[b+2], x[b+3], x[b+4], force,
            dX, dXa, dpm, dpgs, dpt);
    out[b+0] = dX;  out[b+1] = dXa; out[b+2] = dpm;
    out[b+3] = dpgs; out[b+4] = dpt;
}

extern "C" void kernel_launch(void* const* d_in, const int* in_sizes, int n_in,
                              void* d_out, int out_size)
{
    // Identify inputs by size: t has 1 element, x has N*5.
    const float* t_ptr = nullptr;
    const float* x_ptr = nullptr;
    int x_elems = 0;
    for (int k = 0; k < n_in; ++k) {
        if (in_sizes[k] == 1) { t_ptr = (const float*)d_in[k]; }
        else                  { x_ptr = (const float*)d_in[k]; x_elems = in_sizes[k]; }
    }

    int n = x_elems / 5;           // number of rows
    int n_quads = n / 4;           // 4 rows per thread
    int tail_start = n_quads * 4;

    if (n_quads > 0) {
        int threads = 256;
        int blocks = (n_quads + threads - 1) / threads;
        hb_sde_quad_kernel<<<blocks, threads>>>(
            (const float4*)x_ptr, t_ptr, (float4*)d_out, n_quads);
    }
    if (tail_start < n) {
        int tail = n - tail_start;
        hb_sde_tail_kernel<<<(tail + 127) / 128, 128>>>(
            x_ptr, t_ptr, (float*)d_out, tail_start, n);
    }
}

// round 17
// speedup vs baseline: 1.0327x; 1.0101x over previous
#include <cuda_runtime.h>
#include <cuda_bf16.h>

// HairBundleSDE: element-wise RHS of a 5-state SDE over 8,388,608 rows.
// Pure streaming kernel: 167.8 MB in + 167.8 MB out. Strategy: 4 rows
// (20 floats = 80 bytes, always 16B-aligned) per thread via 5x float4
// loads/stores, fully coalesced at the sector level.

#define OMEGA_F   6.28318530717958647692f
#define AMP_F     0.3f

__device__ __forceinline__ void row_rhs(float X, float Xa, float pm, float pgs, float pt,
                                        float force,
                                        float& dX, float& dXa, float& dpm, float& dpgs, float& dpt)
{
    // p_open = sigmoid((X - Xa - D0)/DELTA),  D0=0.5, DELTA=0.2  -> *5
    float z = (X - Xa - 0.5f) * 5.0f;
    float p = 1.0f / (1.0f + __expf(-z));
    // f_gs = K_GS*(X - Xa - D0*p_open), K_GS=0.75
    float fgs = 0.75f * (X - Xa - 0.5f * p);
    // dX = (-f_gs - K_SP*X)/LAM + force, LAM=1, K_SP=0.6
    dX = -fgs - 0.6f * X + force;
    // dXa = (f_gs - F_MAX*(1 - S_CA*pm))/LAM_A, F_MAX=1, S_CA=0.7, LAM_A=10
    dXa = (fgs - (1.0f - 0.7f * pm)) * 0.1f;
    // dpm = (C_M*p*(1-pm) - pm)/TAU_M, C_M=1.5, TAU_M=1
    dpm = 1.5f * p * (1.0f - pm) - pm;
    // dpgs = (C_GS*p*(1-pgs) - pgs)/TAU_GS, C_GS=1.2, TAU_GS=5
    dpgs = (1.2f * p * (1.0f - pgs) - pgs) * 0.2f;
    // dpt = (C_T*p*(1-pt) - pt)/TAU_T, C_T=0.8, TAU_T=10
    dpt = (0.8f * p * (1.0f - pt) - pt) * 0.1f;
}

__global__ void __launch_bounds__(256)
hb_sde_quad_kernel(const float4* __restrict__ x4,
                   const float* __restrict__ t,
                   float4* __restrict__ o4,
                   int n_quads)
{
    int i = blockIdx.x * blockDim.x + threadIdx.x;
    if (i >= n_quads) return;

    float force = AMP_F * sinf(OMEGA_F * t[0]);

    // 4 rows = 20 floats = 5 aligned float4s (base byte offset 80*i, 16B aligned)
    long base = (long)i * 5;
    float4 a = x4[base + 0];
    float4 b = x4[base + 1];
    float4 c = x4[base + 2];
    float4 d = x4[base + 3];
    float4 e = x4[base + 4];

    float v[20] = { a.x, a.y, a.z, a.w,
                    b.x, b.y, b.z, b.w,
                    c.x, c.y, c.z, c.w,
                    d.x, d.y, d.z, d.w,
                    e.x, e.y, e.z, e.w };
    float o[20];

#pragma unroll
    for (int r = 0; r < 4; ++r) {
        row_rhs(v[5*r + 0], v[5*r + 1], v[5*r + 2], v[5*r + 3], v[5*r + 4],
                force,
                o[5*r + 0], o[5*r + 1], o[5*r + 2], o[5*r + 3], o[5*r + 4]);
    }

    o4[base + 0] = make_float4(o[0],  o[1],  o[2],  o[3]);
    o4[base + 1] = make_float4(o[4],  o[5],  o[6],  o[7]);
    o4[base + 2] = make_float4(o[8],  o[9],  o[10], o[11]);
    o4[base + 3] = make_float4(o[12], o[13], o[14], o[15]);
    o4[base + 4] = make_float4(o[16], o[17], o[18], o[19]);
}

// Scalar tail for n % 4 != 0 (not hit at N=8388608, kept for robustness).
__global__ void __launch_bounds__(128)
hb_sde_tail_kernel(const float* __restrict__ x,
                   const float* __restrict__ t,
                   float* __restrict__ out,
                   int start, int n)
{
    int i = start + blockIdx.x * blockDim.x + threadIdx.x;
    if (i >= n) return;

    float force = AMP_F * sinf(OMEGA_F * t[0]);
    long b = (long)i * 5;
    float dX, dXa, dpm, dpgs, dpt;
    row_rhs(x[b+0], x[b+1], x[b+2], x[b+3], x[b+4], force,
            dX, dXa, dpm, dpgs, dpt);
    out[b+0] = dX;  out[b+1] = dXa; out[b+2] = dpm;
    out[b+3] = dpgs; out[b+4] = dpt;
}

extern "C" void kernel_launch(void* const* d_in, const int* in_sizes, int n_in,
                              void* d_out, int out_size)
{
    // Identify inputs by size: t has 1 element, x has N*5.
    const float* t_ptr = nullptr;
    const float* x_ptr = nullptr;
    int x_elems = 0;
    for (int k = 0; k < n_in; ++k) {
        if (in_sizes[k] == 1) { t_ptr = (const float*)d_in[k]; }
        else                  { x_ptr = (const float*)d_in[k]; x_elems = in_sizes[k]; }
    }

    int n = x_elems / 5;           // number of rows
    int n_quads = n / 4;           // 4 rows per thread
    int tail_start = n_quads * 4;

    if (n_quads > 0) {
        int threads = 256;
        int blocks = (n_quads + threads - 1) / threads;
        hb_sde_quad_kernel<<<blocks, threads>>>(
            (const float4*)x_ptr, t_ptr, (float4*)d_out, n_quads);
    }
    if (tail_start < n) {
        int tail = n - tail_start;
        hb_sde_tail_kernel<<<(tail + 127) / 128, 128>>>(
            x_ptr, t_ptr, (float*)d_out, tail_start, n);
    }
}